// round 1
// baseline (speedup 1.0000x reference)
#include <cuda_runtime.h>

#define B_ 8
#define T_ 2048
#define C_ 1024
#define H_ 128

// Scratch for Q, K, V projections (allocation-free rule: device globals)
__device__ float g_Q[B_ * T_ * H_];
__device__ float g_K[B_ * T_ * H_];
__device__ float g_V[B_ * T_ * H_];

// ---------------------------------------------------------------------------
// Kernel 1: QKV projection GEMM.
// X: [16384, 1024] row-major. W: [1024, 128] row-major. out = X @ W.
// BM=128, BN=128(=H), BK=16. 256 threads, 8x8 register micro-tile per thread.
// blockIdx.z selects which of Wq/Wk/Wv (and output buffer).
// ---------------------------------------------------------------------------
__global__ __launch_bounds__(256) void qkv_gemm(
    const float* __restrict__ X,
    const float* __restrict__ Wq,
    const float* __restrict__ Wk,
    const float* __restrict__ Wv)
{
    const float* W  = (blockIdx.z == 0) ? Wq : (blockIdx.z == 1) ? Wk : Wv;
    float*       out = (blockIdx.z == 0) ? g_Q : (blockIdx.z == 1) ? g_K : g_V;

    __shared__ float As[16][132];   // transposed: As[k][m], padded
    __shared__ float Bs[16][132];   // Bs[k][n], padded

    const int tid = threadIdx.x;
    const int tm  = tid >> 4;       // 0..15 -> 8 rows each
    const int tn  = tid & 15;       // 0..15 -> 8 cols each
    const int row0 = blockIdx.x * 128;

    float acc[8][8];
    #pragma unroll
    for (int i = 0; i < 8; i++)
        #pragma unroll
        for (int j = 0; j < 8; j++) acc[i][j] = 0.f;

    const int ar = tid >> 1;          // 0..127 (A row within tile)
    const int ak = (tid & 1) * 8;     // 0 or 8 (A k-offset)
    const int bk = tid >> 4;          // 0..15  (B k row)
    const int bc = (tid & 15) * 8;    // B col

    for (int k0 = 0; k0 < C_; k0 += 16) {
        float4 a0 = *(const float4*)(X + (size_t)(row0 + ar) * C_ + k0 + ak);
        float4 a1 = *(const float4*)(X + (size_t)(row0 + ar) * C_ + k0 + ak + 4);
        float4 b0 = *(const float4*)(W + (size_t)(k0 + bk) * H_ + bc);
        float4 b1 = *(const float4*)(W + (size_t)(k0 + bk) * H_ + bc + 4);

        As[ak + 0][ar] = a0.x; As[ak + 1][ar] = a0.y;
        As[ak + 2][ar] = a0.z; As[ak + 3][ar] = a0.w;
        As[ak + 4][ar] = a1.x; As[ak + 5][ar] = a1.y;
        As[ak + 6][ar] = a1.z; As[ak + 7][ar] = a1.w;
        *(float4*)&Bs[bk][bc]     = b0;
        *(float4*)&Bs[bk][bc + 4] = b1;
        __syncthreads();

        #pragma unroll
        for (int kk = 0; kk < 16; kk++) {
            float a[8], b[8];
            *(float4*)&a[0] = *(float4*)&As[kk][tm * 8];
            *(float4*)&a[4] = *(float4*)&As[kk][tm * 8 + 4];
            *(float4*)&b[0] = *(float4*)&Bs[kk][tn * 8];
            *(float4*)&b[4] = *(float4*)&Bs[kk][tn * 8 + 4];
            #pragma unroll
            for (int i = 0; i < 8; i++)
                #pragma unroll
                for (int j = 0; j < 8; j++)
                    acc[i][j] = fmaf(a[i], b[j], acc[i][j]);
        }
        __syncthreads();
    }

    #pragma unroll
    for (int i = 0; i < 8; i++) {
        float* o = out + (size_t)(row0 + tm * 8 + i) * H_ + tn * 8;
        *(float4*)(o)     = make_float4(acc[i][0], acc[i][1], acc[i][2], acc[i][3]);
        *(float4*)(o + 4) = make_float4(acc[i][4], acc[i][5], acc[i][6], acc[i][7]);
    }
}

// ---------------------------------------------------------------------------
// Kernel 2: causal flash attention, fp32.
// Per block: one (batch, q-tile of 64). Iterate k-tiles of 64 up to diagonal.
// 256 threads as 16(ty) x 16(tx). S fragment: 4 rows x 4 cols (cols strided
// by 16 for bank-conflict-free smem access). O fragment: 4 rows x 8 cols.
// ---------------------------------------------------------------------------
#define QSTRIDE 132
#define PSTRIDE 68
#define ATTN_SMEM_FLOATS (3 * 64 * QSTRIDE + 64 * PSTRIDE)
#define ATTN_SMEM_BYTES  (ATTN_SMEM_FLOATS * 4)

__global__ __launch_bounds__(256) void attn_kernel(float* __restrict__ out)
{
    extern __shared__ float sm[];
    float* Qs = sm;                  // 64 x QSTRIDE (scaled Q)
    float* Ks = Qs + 64 * QSTRIDE;   // 64 x QSTRIDE
    float* Vs = Ks + 64 * QSTRIDE;   // 64 x QSTRIDE
    float* Ps = Vs + 64 * QSTRIDE;   // 64 x PSTRIDE (probabilities)

    const int qt  = 31 - blockIdx.x;   // launch big q-tiles first (load balance)
    const int b   = blockIdx.y;
    const int tid = threadIdx.x;
    const int ty  = tid >> 4;          // 0..15 -> rows 4*ty..4*ty+3
    const int tx  = tid & 15;          // 0..15 -> S cols tx+16j, O cols 8*tx..

    // ---- load Q tile (pre-scaled by C^-0.5 = 1/32) ----
    const float* Qg = g_Q + ((size_t)b * T_ + (size_t)qt * 64) * H_;
    const float scale = 0.03125f;
    #pragma unroll
    for (int p = 0; p < 8; p++) {
        int e = p * 1024 + tid * 4;
        int r = e >> 7, c = e & 127;
        float4 v = *(const float4*)(Qg + r * H_ + c);
        v.x *= scale; v.y *= scale; v.z *= scale; v.w *= scale;
        *(float4*)(Qs + r * QSTRIDE + c) = v;
    }

    float m_run[4], l_run[4], o[4][8];
    #pragma unroll
    for (int i = 0; i < 4; i++) {
        m_run[i] = -1e30f; l_run[i] = 0.f;
        #pragma unroll
        for (int c = 0; c < 8; c++) o[i][c] = 0.f;
    }

    for (int kt = 0; kt <= qt; kt++) {
        __syncthreads();  // previous PV reads of Vs/Ps done before overwrite
        const float* Kg = g_K + ((size_t)b * T_ + (size_t)kt * 64) * H_;
        const float* Vg = g_V + ((size_t)b * T_ + (size_t)kt * 64) * H_;
        #pragma unroll
        for (int p = 0; p < 8; p++) {
            int e = p * 1024 + tid * 4;
            int r = e >> 7, c = e & 127;
            *(float4*)(Ks + r * QSTRIDE + c) = *(const float4*)(Kg + r * H_ + c);
            *(float4*)(Vs + r * QSTRIDE + c) = *(const float4*)(Vg + r * H_ + c);
        }
        __syncthreads();

        // ---- S = Qs @ Ks^T (64x64), fragment 4x4, cols strided by 16 ----
        float s[4][4];
        #pragma unroll
        for (int i = 0; i < 4; i++)
            #pragma unroll
            for (int j = 0; j < 4; j++) s[i][j] = 0.f;

        for (int k = 0; k < H_; k += 4) {
            float4 a[4], bb[4];
            #pragma unroll
            for (int i = 0; i < 4; i++)
                a[i] = *(float4*)(Qs + (4 * ty + i) * QSTRIDE + k);
            #pragma unroll
            for (int j = 0; j < 4; j++)
                bb[j] = *(float4*)(Ks + (tx + 16 * j) * QSTRIDE + k);
            #pragma unroll
            for (int i = 0; i < 4; i++)
                #pragma unroll
                for (int j = 0; j < 4; j++) {
                    s[i][j] = fmaf(a[i].x, bb[j].x, s[i][j]);
                    s[i][j] = fmaf(a[i].y, bb[j].y, s[i][j]);
                    s[i][j] = fmaf(a[i].z, bb[j].z, s[i][j]);
                    s[i][j] = fmaf(a[i].w, bb[j].w, s[i][j]);
                }
        }

        // ---- causal mask (only diagonal tile) ----
        if (kt == qt) {
            #pragma unroll
            for (int i = 0; i < 4; i++)
                #pragma unroll
                for (int j = 0; j < 4; j++)
                    if (tx + 16 * j > 4 * ty + i) s[i][j] = -1e30f;
        }

        // ---- online softmax update (row = 16 lanes sharing a ty group) ----
        #pragma unroll
        for (int i = 0; i < 4; i++) {
            float mt = fmaxf(fmaxf(s[i][0], s[i][1]), fmaxf(s[i][2], s[i][3]));
            #pragma unroll
            for (int off = 8; off > 0; off >>= 1)
                mt = fmaxf(mt, __shfl_xor_sync(0xffffffffu, mt, off));
            float mn = fmaxf(m_run[i], mt);
            float f  = __expf(m_run[i] - mn);
            float rs = 0.f;
            #pragma unroll
            for (int j = 0; j < 4; j++) {
                s[i][j] = __expf(s[i][j] - mn);
                rs += s[i][j];
            }
            #pragma unroll
            for (int off = 8; off > 0; off >>= 1)
                rs += __shfl_xor_sync(0xffffffffu, rs, off);
            l_run[i] = l_run[i] * f + rs;
            m_run[i] = mn;
            #pragma unroll
            for (int c = 0; c < 8; c++) o[i][c] *= f;
        }

        // ---- stage P to smem ----
        #pragma unroll
        for (int i = 0; i < 4; i++)
            #pragma unroll
            for (int j = 0; j < 4; j++)
                Ps[(4 * ty + i) * PSTRIDE + tx + 16 * j] = s[i][j];
        __syncthreads();

        // ---- O += P @ V ----
        for (int k = 0; k < 64; k++) {
            float4 v0 = *(float4*)(Vs + k * QSTRIDE + tx * 8);
            float4 v1 = *(float4*)(Vs + k * QSTRIDE + tx * 8 + 4);
            #pragma unroll
            for (int i = 0; i < 4; i++) {
                float p = Ps[(4 * ty + i) * PSTRIDE + k];
                o[i][0] = fmaf(p, v0.x, o[i][0]);
                o[i][1] = fmaf(p, v0.y, o[i][1]);
                o[i][2] = fmaf(p, v0.z, o[i][2]);
                o[i][3] = fmaf(p, v0.w, o[i][3]);
                o[i][4] = fmaf(p, v1.x, o[i][4]);
                o[i][5] = fmaf(p, v1.y, o[i][5]);
                o[i][6] = fmaf(p, v1.z, o[i][6]);
                o[i][7] = fmaf(p, v1.w, o[i][7]);
            }
        }
    }

    // ---- finalize: divide by l, write out ----
    #pragma unroll
    for (int i = 0; i < 4; i++) {
        float inv = 1.f / l_run[i];
        float* dst = out + ((size_t)b * T_ + (size_t)qt * 64 + 4 * ty + i) * H_ + tx * 8;
        *(float4*)(dst)     = make_float4(o[i][0] * inv, o[i][1] * inv,
                                          o[i][2] * inv, o[i][3] * inv);
        *(float4*)(dst + 4) = make_float4(o[i][4] * inv, o[i][5] * inv,
                                          o[i][6] * inv, o[i][7] * inv);
    }
}

// ---------------------------------------------------------------------------
extern "C" void kernel_launch(void* const* d_in, const int* in_sizes, int n_in,
                              void* d_out, int out_size)
{
    const float* X  = (const float*)d_in[0];  // embeddings [8,2048,1024]
    const float* Wq = (const float*)d_in[1];  // [1024,128]
    const float* Wk = (const float*)d_in[2];
    const float* Wv = (const float*)d_in[3];
    float* out = (float*)d_out;               // [8,2048,128]

    (void)in_sizes; (void)n_in; (void)out_size;

    static int smem_set = 0;
    if (!smem_set) {
        cudaFuncSetAttribute(attn_kernel,
                             cudaFuncAttributeMaxDynamicSharedMemorySize,
                             ATTN_SMEM_BYTES);
        smem_set = 1;
    }

    // QKV projections: grid (M tiles, 1, 3 weights)
    qkv_gemm<<<dim3(T_ * B_ / 128, 1, 3), 256>>>(X, Wq, Wk, Wv);

    // Attention: grid (q-tiles, batch)
    attn_kernel<<<dim3(T_ / 64, B_), 256, ATTN_SMEM_BYTES>>>(out);
}

// round 2
// speedup vs baseline: 3.2345x; 3.2345x over previous
#include <cuda_runtime.h>
#include <cstdint>

#define B_ 8
#define T_ 2048
#define C_ 1024
#define H_ 128

// Scratch for Q, K, V projections (device globals: allocation-free rule)
__device__ float g_Q[B_ * T_ * H_];
__device__ float g_K[B_ * T_ * H_];
__device__ float g_V[B_ * T_ * H_];

// ---------------------------------------------------------------------------
// helpers
// ---------------------------------------------------------------------------
__device__ __forceinline__ uint32_t f2tf(float x) {
    uint32_t u;
    asm("cvt.rna.tf32.f32 %0, %1;" : "=r"(u) : "f"(x));
    return u;
}

__device__ __forceinline__ void mma_tf32(float* c, const uint32_t* a,
                                         uint32_t b0, uint32_t b1) {
    asm volatile(
        "mma.sync.aligned.m16n8k8.row.col.f32.tf32.tf32.f32 "
        "{%0,%1,%2,%3}, {%4,%5,%6,%7}, {%8,%9}, {%0,%1,%2,%3};"
        : "+f"(c[0]), "+f"(c[1]), "+f"(c[2]), "+f"(c[3])
        : "r"(a[0]), "r"(a[1]), "r"(a[2]), "r"(a[3]), "r"(b0), "r"(b1));
}

__device__ __forceinline__ void cp16(void* smem_dst, const void* gmem_src) {
    uint32_t s = (uint32_t)__cvta_generic_to_shared(smem_dst);
    asm volatile("cp.async.cg.shared.global [%0], [%1], 16;" :: "r"(s), "l"(gmem_src));
}
__device__ __forceinline__ void cp_commit() { asm volatile("cp.async.commit_group;"); }
__device__ __forceinline__ void cp_wait0()  { asm volatile("cp.async.wait_group 0;"); }
__device__ __forceinline__ void cp_wait1()  { asm volatile("cp.async.wait_group 1;"); }

// ---------------------------------------------------------------------------
// Kernel 1: QKV projection GEMM (tf32 tensor cores).
// X:[16384,1024] fp32, W:[1024,128]. out = X @ W, emitted tf32-rounded
// (Q additionally pre-scaled by C^-0.5 = 1/32).
// Block 128x128, 8 warps (warp tile 32x64), K-tile 32, cp.async double buffer.
// ---------------------------------------------------------------------------
#define PA 36    // As stride (k), 36 mod 32 = 4 -> conflict-free frag loads
#define PB 136   // Bs stride (n), 136 mod 32 = 8 -> conflict-free frag loads
#define PROJ_BUF_FLOATS (128 * PA + 32 * PB)
#define PROJ_SMEM_BYTES (2 * PROJ_BUF_FLOATS * 4)

__global__ __launch_bounds__(256, 2) void qkv_gemm(
    const float* __restrict__ X,
    const float* __restrict__ Wq,
    const float* __restrict__ Wk,
    const float* __restrict__ Wv)
{
    extern __shared__ float sm[];
    const int z = blockIdx.z;
    const float* W  = (z == 0) ? Wq : (z == 1) ? Wk : Wv;
    float*      out = (z == 0) ? g_Q : (z == 1) ? g_K : g_V;
    const float osc = (z == 0) ? 0.03125f : 1.0f;

    const int tid  = threadIdx.x;
    const int lane = tid & 31;
    const int warp = tid >> 5;
    const int wm   = (warp & 3) * 32;   // warp row offset
    const int wn   = (warp >> 2) * 64;  // warp col offset
    const int row0 = blockIdx.x * 128;
    const int g    = lane >> 2;         // 0..7
    const int q4   = lane & 3;          // 0..3

    float acc[2][8][4];
    #pragma unroll
    for (int mt = 0; mt < 2; mt++)
        #pragma unroll
        for (int nt = 0; nt < 8; nt++)
            #pragma unroll
            for (int i = 0; i < 4; i++) acc[mt][nt][i] = 0.f;

    // async tile loaders (raw fp32; cvt at fragment load)
    auto issue = [&](int kt, int buf) {
        float* As = sm + buf * PROJ_BUF_FLOATS;
        float* Bs = As + 128 * PA;
        int k0 = kt * 32;
        #pragma unroll
        for (int p = 0; p < 4; p++) {           // A: 128x32 = 1024 float4
            int fid = tid + 256 * p;
            int r = fid >> 3, c = (fid & 7) * 4;
            cp16(&As[r * PA + c], X + (size_t)(row0 + r) * C_ + k0 + c);
        }
        #pragma unroll
        for (int p = 0; p < 4; p++) {           // B: 32x128 = 1024 float4
            int fid = tid + 256 * p;
            int k = fid >> 5, n = (fid & 31) * 4;
            cp16(&Bs[k * PB + n], W + (size_t)(k0 + k) * H_ + n);
        }
    };

    issue(0, 0);
    cp_commit();

    for (int kt = 0; kt < 32; kt++) {
        if (kt < 31) {
            issue(kt + 1, (kt + 1) & 1);
            cp_commit();
            cp_wait1();
        } else {
            cp_wait0();
        }
        __syncthreads();

        const float* As = sm + (kt & 1) * PROJ_BUF_FLOATS;
        const float* Bs = As + 128 * PA;

        #pragma unroll
        for (int k8 = 0; k8 < 32; k8 += 8) {
            uint32_t a[2][4];
            #pragma unroll
            for (int mt = 0; mt < 2; mt++) {
                int r = wm + mt * 16 + g;
                a[mt][0] = f2tf(As[r * PA + k8 + q4]);
                a[mt][1] = f2tf(As[(r + 8) * PA + k8 + q4]);
                a[mt][2] = f2tf(As[r * PA + k8 + 4 + q4]);
                a[mt][3] = f2tf(As[(r + 8) * PA + k8 + 4 + q4]);
            }
            #pragma unroll
            for (int nt = 0; nt < 8; nt++) {
                int cn = wn + nt * 8 + g;
                uint32_t b0 = f2tf(Bs[(k8 + q4) * PB + cn]);
                uint32_t b1 = f2tf(Bs[(k8 + 4 + q4) * PB + cn]);
                mma_tf32(acc[0][nt], a[0], b0, b1);
                mma_tf32(acc[1][nt], a[1], b0, b1);
            }
        }
        __syncthreads();
    }

    // epilogue: tf32-rounded (Q pre-scaled) so attention skips all cvt
    #pragma unroll
    for (int mt = 0; mt < 2; mt++) {
        int r = row0 + wm + mt * 16 + g;
        #pragma unroll
        for (int nt = 0; nt < 8; nt++) {
            int cn = wn + nt * 8 + 2 * q4;
            float2 v0, v1;
            v0.x = __uint_as_float(f2tf(acc[mt][nt][0] * osc));
            v0.y = __uint_as_float(f2tf(acc[mt][nt][1] * osc));
            v1.x = __uint_as_float(f2tf(acc[mt][nt][2] * osc));
            v1.y = __uint_as_float(f2tf(acc[mt][nt][3] * osc));
            *(float2*)(out + (size_t)r * H_ + cn)       = v0;
            *(float2*)(out + (size_t)(r + 8) * H_ + cn) = v1;
        }
    }
}

// ---------------------------------------------------------------------------
// Kernel 2: causal flash attention, tf32 tensor cores.
// BQ=64, BK=64, 4 warps (16 q-rows each). Q fragments resident in registers.
// smem: K (64x132), V (64x136), P (64x68) = 84KB -> 2 CTAs/SM.
// ---------------------------------------------------------------------------
#define KS_STR 132   // 132 mod 32 = 4
#define VS_STR 136   // 136 mod 32 = 8
#define PS_STR 68    // 68  mod 32 = 4
#define ATTN_SMEM_FLOATS (64 * KS_STR + 64 * VS_STR + 64 * PS_STR)
#define ATTN_SMEM_BYTES  (ATTN_SMEM_FLOATS * 4)

__global__ __launch_bounds__(128, 2) void attn_kernel(float* __restrict__ out)
{
    extern __shared__ float sm[];
    float* Ks = sm;
    float* Vs = Ks + 64 * KS_STR;
    float* Ps = Vs + 64 * VS_STR;
    const uint32_t* Ksu = (const uint32_t*)Ks;
    const uint32_t* Vsu = (const uint32_t*)Vs;
    const uint32_t* Psu = (const uint32_t*)Ps;

    const int qt   = 31 - blockIdx.x;   // big q-tiles first
    const int b    = blockIdx.y;
    const int tid  = threadIdx.x;
    const int lane = tid & 31;
    const int w    = tid >> 5;          // warp -> q rows w*16..w*16+15
    const int g    = lane >> 2;
    const int q4   = lane & 3;

    // Q fragments for all 16 k8-steps (values already tf32 + scaled)
    uint32_t qa[16][4];
    {
        const uint32_t* Qg = (const uint32_t*)g_Q +
            ((size_t)b * T_ + (size_t)qt * 64 + w * 16) * H_;
        #pragma unroll
        for (int ks = 0; ks < 16; ks++) {
            qa[ks][0] = Qg[g * H_ + ks * 8 + q4];
            qa[ks][1] = Qg[(g + 8) * H_ + ks * 8 + q4];
            qa[ks][2] = Qg[g * H_ + ks * 8 + 4 + q4];
            qa[ks][3] = Qg[(g + 8) * H_ + ks * 8 + 4 + q4];
        }
    }

    float m_run[2] = {-1e30f, -1e30f};
    float l_run[2] = {0.f, 0.f};
    float o[16][4];
    #pragma unroll
    for (int nt = 0; nt < 16; nt++)
        #pragma unroll
        for (int i = 0; i < 4; i++) o[nt][i] = 0.f;

    const int prow = w * 16 + g;

    for (int kt = 0; kt <= qt; kt++) {
        __syncthreads();   // prior iter done reading Ks/Vs
        {
            const float* Kg = g_K + ((size_t)b * T_ + (size_t)kt * 64) * H_;
            const float* Vg = g_V + ((size_t)b * T_ + (size_t)kt * 64) * H_;
            #pragma unroll
            for (int p = 0; p < 16; p++) {      // 64x128 = 2048 float4 per mat
                int fid = tid + 128 * p;
                int r = fid >> 5, c = (fid & 31) * 4;
                cp16(&Ks[r * KS_STR + c], Kg + r * H_ + c);
                cp16(&Vs[r * VS_STR + c], Vg + r * H_ + c);
            }
            cp_commit();
            cp_wait0();
        }
        __syncthreads();

        // ---- S = Q K^T : warp computes 16x64 ----
        float s[8][4];
        #pragma unroll
        for (int nt = 0; nt < 8; nt++)
            #pragma unroll
            for (int i = 0; i < 4; i++) s[nt][i] = 0.f;

        #pragma unroll
        for (int ks = 0; ks < 16; ks++) {
            #pragma unroll
            for (int nt = 0; nt < 8; nt++) {
                uint32_t b0 = Ksu[(nt * 8 + g) * KS_STR + ks * 8 + q4];
                uint32_t b1 = Ksu[(nt * 8 + g) * KS_STR + ks * 8 + 4 + q4];
                mma_tf32(s[nt], qa[ks], b0, b1);
            }
        }

        // ---- causal mask on diagonal tile ----
        if (kt == qt) {
            #pragma unroll
            for (int nt = 0; nt < 8; nt++) {
                int c0 = nt * 8 + 2 * q4;
                if (c0     > prow)     s[nt][0] = -1e30f;
                if (c0 + 1 > prow)     s[nt][1] = -1e30f;
                if (c0     > prow + 8) s[nt][2] = -1e30f;
                if (c0 + 1 > prow + 8) s[nt][3] = -1e30f;
            }
        }

        // ---- online softmax (rows prow and prow+8, quad reductions) ----
        #pragma unroll
        for (int h = 0; h < 2; h++) {
            float mt = -1e30f;
            #pragma unroll
            for (int nt = 0; nt < 8; nt++)
                mt = fmaxf(mt, fmaxf(s[nt][2 * h], s[nt][2 * h + 1]));
            mt = fmaxf(mt, __shfl_xor_sync(0xffffffffu, mt, 1));
            mt = fmaxf(mt, __shfl_xor_sync(0xffffffffu, mt, 2));
            float mn = fmaxf(m_run[h], mt);
            float f  = __expf(m_run[h] - mn);
            m_run[h] = mn;
            float rs = 0.f;
            #pragma unroll
            for (int nt = 0; nt < 8; nt++) {
                s[nt][2 * h]     = __expf(s[nt][2 * h] - mn);
                s[nt][2 * h + 1] = __expf(s[nt][2 * h + 1] - mn);
                rs += s[nt][2 * h] + s[nt][2 * h + 1];
            }
            rs += __shfl_xor_sync(0xffffffffu, rs, 1);
            rs += __shfl_xor_sync(0xffffffffu, rs, 2);
            l_run[h] = l_run[h] * f + rs;
            #pragma unroll
            for (int nt = 0; nt < 16; nt++) {
                o[nt][2 * h]     *= f;
                o[nt][2 * h + 1] *= f;
            }
        }

        // ---- stage P (tf32) ----
        #pragma unroll
        for (int nt = 0; nt < 8; nt++) {
            int c0 = nt * 8 + 2 * q4;
            Ps[prow * PS_STR + c0]           = __uint_as_float(f2tf(s[nt][0]));
            Ps[prow * PS_STR + c0 + 1]       = __uint_as_float(f2tf(s[nt][1]));
            Ps[(prow + 8) * PS_STR + c0]     = __uint_as_float(f2tf(s[nt][2]));
            Ps[(prow + 8) * PS_STR + c0 + 1] = __uint_as_float(f2tf(s[nt][3]));
        }
        __syncwarp();   // warp-local: each warp reads only its own P rows

        // ---- O += P V : warp computes 16x128 ----
        #pragma unroll
        for (int ks = 0; ks < 8; ks++) {
            uint32_t a[4];
            a[0] = Psu[prow * PS_STR + ks * 8 + q4];
            a[1] = Psu[(prow + 8) * PS_STR + ks * 8 + q4];
            a[2] = Psu[prow * PS_STR + ks * 8 + 4 + q4];
            a[3] = Psu[(prow + 8) * PS_STR + ks * 8 + 4 + q4];
            #pragma unroll
            for (int nt = 0; nt < 16; nt++) {
                uint32_t b0 = Vsu[(ks * 8 + q4) * VS_STR + nt * 8 + g];
                uint32_t b1 = Vsu[(ks * 8 + 4 + q4) * VS_STR + nt * 8 + g];
                mma_tf32(o[nt], a, b0, b1);
            }
        }
    }

    // ---- finalize ----
    float inv0 = 1.f / l_run[0];
    float inv1 = 1.f / l_run[1];
    size_t r = (size_t)b * T_ + (size_t)qt * 64 + w * 16 + g;
    #pragma unroll
    for (int nt = 0; nt < 16; nt++) {
        int cn = nt * 8 + 2 * q4;
        float2 v0, v1;
        v0.x = o[nt][0] * inv0; v0.y = o[nt][1] * inv0;
        v1.x = o[nt][2] * inv1; v1.y = o[nt][3] * inv1;
        *(float2*)(out + r * H_ + cn)       = v0;
        *(float2*)(out + (r + 8) * H_ + cn) = v1;
    }
}

// ---------------------------------------------------------------------------
extern "C" void kernel_launch(void* const* d_in, const int* in_sizes, int n_in,
                              void* d_out, int out_size)
{
    const float* X  = (const float*)d_in[0];
    const float* Wq = (const float*)d_in[1];
    const float* Wk = (const float*)d_in[2];
    const float* Wv = (const float*)d_in[3];
    float* out = (float*)d_out;
    (void)in_sizes; (void)n_in; (void)out_size;

    static int smem_set = 0;
    if (!smem_set) {
        cudaFuncSetAttribute(qkv_gemm,
                             cudaFuncAttributeMaxDynamicSharedMemorySize,
                             PROJ_SMEM_BYTES);
        cudaFuncSetAttribute(attn_kernel,
                             cudaFuncAttributeMaxDynamicSharedMemorySize,
                             ATTN_SMEM_BYTES);
        smem_set = 1;
    }

    qkv_gemm<<<dim3(T_ * B_ / 128, 1, 3), 256, PROJ_SMEM_BYTES>>>(X, Wq, Wk, Wv);
    attn_kernel<<<dim3(T_ / 64, B_), 128, ATTN_SMEM_BYTES>>>(out);
}

// round 3
// speedup vs baseline: 3.7316x; 1.1537x over previous
#include <cuda_runtime.h>
#include <cstdint>

#define B_ 8
#define T_ 2048
#define C_ 1024
#define H_ 128

// Scratch (device globals: allocation-free rule)
__device__ float g_Q[B_ * T_ * H_];
__device__ float g_K[B_ * T_ * H_];
__device__ float g_V[B_ * T_ * H_];
__device__ float g_Wt[3][C_ * H_];   // tf32-rounded weights

// ---------------------------------------------------------------------------
// helpers
// ---------------------------------------------------------------------------
__device__ __forceinline__ uint32_t f2tf(float x) {
    uint32_t u;
    asm("cvt.rna.tf32.f32 %0, %1;" : "=r"(u) : "f"(x));
    return u;
}

__device__ __forceinline__ void mma_tf32(float* c, const uint32_t* a,
                                         uint32_t b0, uint32_t b1) {
    asm volatile(
        "mma.sync.aligned.m16n8k8.row.col.f32.tf32.tf32.f32 "
        "{%0,%1,%2,%3}, {%4,%5,%6,%7}, {%8,%9}, {%0,%1,%2,%3};"
        : "+f"(c[0]), "+f"(c[1]), "+f"(c[2]), "+f"(c[3])
        : "r"(a[0]), "r"(a[1]), "r"(a[2]), "r"(a[3]), "r"(b0), "r"(b1));
}

__device__ __forceinline__ void cp16(void* smem_dst, const void* gmem_src) {
    uint32_t s = (uint32_t)__cvta_generic_to_shared(smem_dst);
    asm volatile("cp.async.cg.shared.global [%0], [%1], 16;" :: "r"(s), "l"(gmem_src));
}
__device__ __forceinline__ void cp_commit() { asm volatile("cp.async.commit_group;"); }
__device__ __forceinline__ void cp_wait0()  { asm volatile("cp.async.wait_group 0;"); }
__device__ __forceinline__ void cp_wait1()  { asm volatile("cp.async.wait_group 1;"); }

// ---------------------------------------------------------------------------
// Kernel 0: round W to tf32 once (removes cvts from the GEMM inner loop)
// ---------------------------------------------------------------------------
__global__ void conv_w(const float* __restrict__ Wq,
                       const float* __restrict__ Wk,
                       const float* __restrict__ Wv)
{
    int i = (blockIdx.x * 256 + threadIdx.x) * 4;      // float4 index
    const float* src = (i < C_ * H_) ? Wq : (i < 2 * C_ * H_) ? Wk : Wv;
    int off = i % (C_ * H_);
    float4 v = *(const float4*)(src + off);
    uint4 o;
    o.x = f2tf(v.x); o.y = f2tf(v.y); o.z = f2tf(v.z); o.w = f2tf(v.w);
    *(uint4*)(&g_Wt[0][0] + i) = o;
}

// ---------------------------------------------------------------------------
// Kernel 1: QKV projection GEMM (tf32 tensor cores).
// Block 128x128, 8 warps (warp 32x64), K-tile 32, cp.async double buffer.
// B-side reads pre-rounded tf32 bits (no cvt); A-side cvt at frag load.
// ---------------------------------------------------------------------------
#define PA 36
#define PB 136
#define PROJ_BUF_FLOATS (128 * PA + 32 * PB)
#define PROJ_SMEM_BYTES (2 * PROJ_BUF_FLOATS * 4)

__global__ __launch_bounds__(256, 2) void qkv_gemm(const float* __restrict__ X)
{
    extern __shared__ float sm[];
    const int z = blockIdx.z;
    const float* W  = &g_Wt[z][0];
    float*      out = (z == 0) ? g_Q : (z == 1) ? g_K : g_V;
    const float osc = (z == 0) ? 0.03125f : 1.0f;

    const int tid  = threadIdx.x;
    const int lane = tid & 31;
    const int warp = tid >> 5;
    const int wm   = (warp & 3) * 32;
    const int wn   = (warp >> 2) * 64;
    const int row0 = blockIdx.x * 128;
    const int g    = lane >> 2;
    const int q4   = lane & 3;

    float acc[2][8][4];
    #pragma unroll
    for (int mt = 0; mt < 2; mt++)
        #pragma unroll
        for (int nt = 0; nt < 8; nt++)
            #pragma unroll
            for (int i = 0; i < 4; i++) acc[mt][nt][i] = 0.f;

    auto issue = [&](int kt, int buf) {
        float* As = sm + buf * PROJ_BUF_FLOATS;
        float* Bs = As + 128 * PA;
        int k0 = kt * 32;
        #pragma unroll
        for (int p = 0; p < 4; p++) {
            int fid = tid + 256 * p;
            int r = fid >> 3, c = (fid & 7) * 4;
            cp16(&As[r * PA + c], X + (size_t)(row0 + r) * C_ + k0 + c);
        }
        #pragma unroll
        for (int p = 0; p < 4; p++) {
            int fid = tid + 256 * p;
            int k = fid >> 5, n = (fid & 31) * 4;
            cp16(&Bs[k * PB + n], W + (size_t)(k0 + k) * H_ + n);
        }
    };

    issue(0, 0);
    cp_commit();

    for (int kt = 0; kt < 32; kt++) {
        if (kt < 31) {
            issue(kt + 1, (kt + 1) & 1);
            cp_commit();
            cp_wait1();
        } else {
            cp_wait0();
        }
        __syncthreads();

        const float*    As  = sm + (kt & 1) * PROJ_BUF_FLOATS;
        const uint32_t* Bsu = (const uint32_t*)(As + 128 * PA);

        #pragma unroll
        for (int k8 = 0; k8 < 32; k8 += 8) {
            uint32_t a[2][4];
            #pragma unroll
            for (int mt = 0; mt < 2; mt++) {
                int r = wm + mt * 16 + g;
                a[mt][0] = f2tf(As[r * PA + k8 + q4]);
                a[mt][1] = f2tf(As[(r + 8) * PA + k8 + q4]);
                a[mt][2] = f2tf(As[r * PA + k8 + 4 + q4]);
                a[mt][3] = f2tf(As[(r + 8) * PA + k8 + 4 + q4]);
            }
            #pragma unroll
            for (int nt = 0; nt < 8; nt++) {
                int cn = wn + nt * 8 + g;
                uint32_t b0 = Bsu[(k8 + q4) * PB + cn];        // pre-rounded
                uint32_t b1 = Bsu[(k8 + 4 + q4) * PB + cn];
                mma_tf32(acc[0][nt], a[0], b0, b1);
                mma_tf32(acc[1][nt], a[1], b0, b1);
            }
        }
        __syncthreads();
    }

    #pragma unroll
    for (int mt = 0; mt < 2; mt++) {
        int r = row0 + wm + mt * 16 + g;
        #pragma unroll
        for (int nt = 0; nt < 8; nt++) {
            int cn = wn + nt * 8 + 2 * q4;
            float2 v0, v1;
            v0.x = __uint_as_float(f2tf(acc[mt][nt][0] * osc));
            v0.y = __uint_as_float(f2tf(acc[mt][nt][1] * osc));
            v1.x = __uint_as_float(f2tf(acc[mt][nt][2] * osc));
            v1.y = __uint_as_float(f2tf(acc[mt][nt][3] * osc));
            *(float2*)(out + (size_t)r * H_ + cn)       = v0;
            *(float2*)(out + (size_t)(r + 8) * H_ + cn) = v1;
        }
    }
}

// ---------------------------------------------------------------------------
// Kernel 2: causal flash attention, tf32 tensor cores.
// BQ=128 (8 warps x 16 q-rows), BK=64, double-buffered cp.async K/V pipeline.
// smem: 2*K(64x132) + 2*V(64x136) + P(128x68) = 168KB. 1 CTA/SM, 2 warps/SMSP.
// ---------------------------------------------------------------------------
#define KS_STR 132
#define VS_STR 136
#define PS_STR 68
#define ATTN_SMEM_FLOATS (2 * 64 * KS_STR + 2 * 64 * VS_STR + 128 * PS_STR)
#define ATTN_SMEM_BYTES  (ATTN_SMEM_FLOATS * 4)

__global__ __launch_bounds__(256, 1) void attn_kernel(float* __restrict__ out)
{
    extern __shared__ float sm[];
    float* Ks = sm;                      // [2][64][KS_STR]
    float* Vs = Ks + 2 * 64 * KS_STR;    // [2][64][VS_STR]
    float* Ps = Vs + 2 * 64 * VS_STR;    // [128][PS_STR]
    const uint32_t* Psu = (const uint32_t*)Ps;

    const int qt   = 15 - blockIdx.x;    // big q-tiles first
    const int b    = blockIdx.y;
    const int tid  = threadIdx.x;
    const int lane = tid & 31;
    const int w    = tid >> 5;           // warp -> q rows w*16..w*16+15
    const int g    = lane >> 2;
    const int q4   = lane & 3;
    const int nkt  = 2 * qt + 2;         // k-tiles of 64

    // Q fragments resident (values already tf32 + scaled by 1/32)
    uint32_t qa[16][4];
    {
        const uint32_t* Qg = (const uint32_t*)g_Q +
            ((size_t)b * T_ + (size_t)qt * 128 + w * 16) * H_;
        #pragma unroll
        for (int ks = 0; ks < 16; ks++) {
            qa[ks][0] = Qg[g * H_ + ks * 8 + q4];
            qa[ks][1] = Qg[(g + 8) * H_ + ks * 8 + q4];
            qa[ks][2] = Qg[g * H_ + ks * 8 + 4 + q4];
            qa[ks][3] = Qg[(g + 8) * H_ + ks * 8 + 4 + q4];
        }
    }

    float m_run[2] = {-1e30f, -1e30f};
    float l_run[2] = {0.f, 0.f};
    float o[16][4];
    #pragma unroll
    for (int nt = 0; nt < 16; nt++)
        #pragma unroll
        for (int i = 0; i < 4; i++) o[nt][i] = 0.f;

    const int prow = w * 16 + g;

    auto issue = [&](int kt) {
        int buf = kt & 1;
        float* Kd = Ks + buf * 64 * KS_STR;
        float* Vd = Vs + buf * 64 * VS_STR;
        const float* Kg = g_K + ((size_t)b * T_ + (size_t)kt * 64) * H_;
        const float* Vg = g_V + ((size_t)b * T_ + (size_t)kt * 64) * H_;
        #pragma unroll
        for (int p = 0; p < 8; p++) {        // 64x128 = 2048 float4 per matrix
            int fid = tid + 256 * p;
            int r = fid >> 5, c = (fid & 31) * 4;
            cp16(&Kd[r * KS_STR + c], Kg + r * H_ + c);
            cp16(&Vd[r * VS_STR + c], Vg + r * H_ + c);
        }
    };

    issue(0);
    cp_commit();

    for (int kt = 0; kt < nkt; kt++) {
        if (kt < nkt - 1) {
            issue(kt + 1);      // prefetch into other buffer (safe: end-of-iter sync)
            cp_commit();
            cp_wait1();
        } else {
            cp_wait0();
        }
        __syncthreads();

        const uint32_t* Ksu = (const uint32_t*)(Ks + (kt & 1) * 64 * KS_STR);
        const uint32_t* Vsu = (const uint32_t*)(Vs + (kt & 1) * 64 * VS_STR);

        // rel = q-row base of this warp minus k-col base (global diagonal offset)
        const int rel = qt * 128 + w * 16 - kt * 64;
        const bool fully_masked = (rel < -15);

        if (!fully_masked) {
            // ---- S = Q K^T : warp computes 16x64 ----
            float s[8][4];
            #pragma unroll
            for (int nt = 0; nt < 8; nt++)
                #pragma unroll
                for (int i = 0; i < 4; i++) s[nt][i] = 0.f;

            #pragma unroll
            for (int ks = 0; ks < 16; ks++) {
                #pragma unroll
                for (int nt = 0; nt < 8; nt++) {
                    uint32_t b0 = Ksu[(nt * 8 + g) * KS_STR + ks * 8 + q4];
                    uint32_t b1 = Ksu[(nt * 8 + g) * KS_STR + ks * 8 + 4 + q4];
                    mma_tf32(s[nt], qa[ks], b0, b1);
                }
            }

            // ---- causal mask: col > row  <=>  c > rel + g (resp. +8) ----
            if (rel < 64) {
                #pragma unroll
                for (int nt = 0; nt < 8; nt++) {
                    int c0 = nt * 8 + 2 * q4;
                    if (c0     > rel + g)     s[nt][0] = -1e30f;
                    if (c0 + 1 > rel + g)     s[nt][1] = -1e30f;
                    if (c0     > rel + g + 8) s[nt][2] = -1e30f;
                    if (c0 + 1 > rel + g + 8) s[nt][3] = -1e30f;
                }
            }

            // ---- online softmax (quad reductions; rows g, g+8) ----
            #pragma unroll
            for (int h = 0; h < 2; h++) {
                float mt = -1e30f;
                #pragma unroll
                for (int nt = 0; nt < 8; nt++)
                    mt = fmaxf(mt, fmaxf(s[nt][2 * h], s[nt][2 * h + 1]));
                mt = fmaxf(mt, __shfl_xor_sync(0xffffffffu, mt, 1));
                mt = fmaxf(mt, __shfl_xor_sync(0xffffffffu, mt, 2));
                float mn = fmaxf(m_run[h], mt);
                float f  = __expf(m_run[h] - mn);
                m_run[h] = mn;
                float rs = 0.f;
                #pragma unroll
                for (int nt = 0; nt < 8; nt++) {
                    s[nt][2 * h]     = __expf(s[nt][2 * h] - mn);
                    s[nt][2 * h + 1] = __expf(s[nt][2 * h + 1] - mn);
                    rs += s[nt][2 * h] + s[nt][2 * h + 1];
                }
                rs += __shfl_xor_sync(0xffffffffu, rs, 1);
                rs += __shfl_xor_sync(0xffffffffu, rs, 2);
                l_run[h] = l_run[h] * f + rs;
                #pragma unroll
                for (int nt = 0; nt < 16; nt++) {
                    o[nt][2 * h]     *= f;
                    o[nt][2 * h + 1] *= f;
                }
            }

            // ---- stage P (tf32) ----
            float* Pw = Ps;
            #pragma unroll
            for (int nt = 0; nt < 8; nt++) {
                int c0 = nt * 8 + 2 * q4;
                Pw[prow * PS_STR + c0]           = __uint_as_float(f2tf(s[nt][0]));
                Pw[prow * PS_STR + c0 + 1]       = __uint_as_float(f2tf(s[nt][1]));
                Pw[(prow + 8) * PS_STR + c0]     = __uint_as_float(f2tf(s[nt][2]));
                Pw[(prow + 8) * PS_STR + c0 + 1] = __uint_as_float(f2tf(s[nt][3]));
            }
            __syncwarp();       // each warp reads only its own 16 P rows

            // ---- O += P V : warp computes 16x128 ----
            #pragma unroll
            for (int ks = 0; ks < 8; ks++) {
                uint32_t a[4];
                a[0] = Psu[prow * PS_STR + ks * 8 + q4];
                a[1] = Psu[(prow + 8) * PS_STR + ks * 8 + q4];
                a[2] = Psu[prow * PS_STR + ks * 8 + 4 + q4];
                a[3] = Psu[(prow + 8) * PS_STR + ks * 8 + 4 + q4];
                #pragma unroll
                for (int nt = 0; nt < 16; nt++) {
                    uint32_t b0 = Vsu[(ks * 8 + q4) * VS_STR + nt * 8 + g];
                    uint32_t b1 = Vsu[(ks * 8 + 4 + q4) * VS_STR + nt * 8 + g];
                    mma_tf32(o[nt], a, b0, b1);
                }
            }
        }
        __syncthreads();        // all warps done reading this buffer
    }

    // ---- finalize ----
    float inv0 = 1.f / l_run[0];
    float inv1 = 1.f / l_run[1];
    size_t r = (size_t)b * T_ + (size_t)qt * 128 + w * 16 + g;
    #pragma unroll
    for (int nt = 0; nt < 16; nt++) {
        int cn = nt * 8 + 2 * q4;
        float2 v0, v1;
        v0.x = o[nt][0] * inv0; v0.y = o[nt][1] * inv0;
        v1.x = o[nt][2] * inv1; v1.y = o[nt][3] * inv1;
        *(float2*)(out + r * H_ + cn)       = v0;
        *(float2*)(out + (r + 8) * H_ + cn) = v1;
    }
}

// ---------------------------------------------------------------------------
extern "C" void kernel_launch(void* const* d_in, const int* in_sizes, int n_in,
                              void* d_out, int out_size)
{
    const float* X  = (const float*)d_in[0];
    const float* Wq = (const float*)d_in[1];
    const float* Wk = (const float*)d_in[2];
    const float* Wv = (const float*)d_in[3];
    float* out = (float*)d_out;
    (void)in_sizes; (void)n_in; (void)out_size;

    static int smem_set = 0;
    if (!smem_set) {
        cudaFuncSetAttribute(qkv_gemm,
                             cudaFuncAttributeMaxDynamicSharedMemorySize,
                             PROJ_SMEM_BYTES);
        cudaFuncSetAttribute(attn_kernel,
                             cudaFuncAttributeMaxDynamicSharedMemorySize,
                             ATTN_SMEM_BYTES);
        smem_set = 1;
    }

    conv_w<<<3 * C_ * H_ / (256 * 4), 256>>>(Wq, Wk, Wv);
    qkv_gemm<<<dim3(T_ * B_ / 128, 1, 3), 256, PROJ_SMEM_BYTES>>>(X);
    attn_kernel<<<dim3(T_ / 128, B_), 256, ATTN_SMEM_BYTES>>>(out);
}